// round 9
// baseline (speedup 1.0000x reference)
#include <cuda_runtime.h>
#include <math.h>

#define NB 128
#define NP 625
#define NENC 512
#define NA 256
#define NE 256
#define NH 512
#define NV 70
#define NT 70
#define NG 2048
#define KC 64
#define START_TOK 68
#define END_TOK 69

// ---------------- scratch ----------------
__device__ float g_att1[NB * NP * NA];   // 81.92MB
__device__ float g_h[NB * NH];
__device__ float g_c[NB * NH];
__device__ float g_mean[NB * NENC];
__device__ float g_x[NB * NH];           // gated awe
__device__ float g_e[NB * NP];           // attention energies
__device__ float g_a2p[4][NB * NA];      // att2 K-partials
__device__ float g_gtp[4][NB * NENC];    // gate  K-partials
__device__ float g_gw[2][NB * NG];       // h@Whh K-partials
__device__ float g_wp[2][NB * NG];       // awe@Wih2 K-partials
__device__ float g_embW[NV * NG];        // emb @ Wih[0:256] per vocab token
__device__ float g_lstmb[NG];            // bih + bhh
__device__ float g_WfcT[NV * NH];
__device__ float g_rowval[NB];
__device__ int   g_rowflat[NB];
__device__ int   g_tok[NB];
__device__ int   g_done[1];

// ---------------- f32x2 helpers ----------------
__device__ __forceinline__ unsigned long long fma2(unsigned long long a, unsigned long long b,
                                                   unsigned long long c) {
    unsigned long long d;
    asm("fma.rn.f32x2 %0, %1, %2, %3;" : "=l"(d) : "l"(a), "l"(b), "l"(c));
    return d;
}
__device__ __forceinline__ float2 unpack2(unsigned long long v) {
    float2 r;
    asm("mov.b64 {%0, %1}, %2;" : "=f"(r.x), "=f"(r.y) : "l"(v));
    return r;
}
__device__ __forceinline__ float sigmoidf_(float x) { return 1.f / (1.f + expf(-x)); }

// ---------------- core GEMM tile: C[128, c0:c0+32] = A[128,K] @ W[K, ldw] ----------------
__device__ __forceinline__ void gemm128x32(const float* __restrict__ A, int lda,
                                           const float* __restrict__ W, int ldw, int c0, int K,
                                           unsigned long long acc[8], float* As, float2* Bs) {
    const int tid = threadIdx.x;
    const int ai = (tid >> 4) * 2;
    const int bi = tid & 15;
    const int la_m = tid & 127, la_k = (tid >> 7) * 32;
    const int lb_n = tid & 31, lb_k = tid >> 5;
#pragma unroll
    for (int j = 0; j < 8; j++) acc[j] = 0ULL;
    float4 pa[8];
    float pb[8];
    const float* Arow = A + (size_t)la_m * lda + la_k;
    const float* Wcol = W + (size_t)lb_k * ldw + c0 + lb_n;
#pragma unroll
    for (int j = 0; j < 8; j++) pa[j] = *(const float4*)(Arow + 4 * j);
#pragma unroll
    for (int j = 0; j < 8; j++) pb[j] = Wcol[(size_t)(8 * j) * ldw];
    const int nc = K / KC;
    for (int ch = 0;;) {
#pragma unroll
        for (int j = 0; j < 8; j++) {
            float4 v = pa[j];
            int kk = la_k + 4 * j;
            As[(kk + 0) * 128 + la_m] = v.x;
            As[(kk + 1) * 128 + la_m] = v.y;
            As[(kk + 2) * 128 + la_m] = v.z;
            As[(kk + 3) * 128 + la_m] = v.w;
        }
#pragma unroll
        for (int j = 0; j < 8; j++) Bs[(lb_k + 8 * j) * 32 + lb_n] = make_float2(pb[j], pb[j]);
        __syncthreads();
        if (ch + 1 < nc) {
            const float* Ar2 = Arow + (ch + 1) * KC;
            const float* Wc2 = Wcol + (size_t)((ch + 1) * KC) * ldw;
#pragma unroll
            for (int j = 0; j < 8; j++) pa[j] = *(const float4*)(Ar2 + 4 * j);
#pragma unroll
            for (int j = 0; j < 8; j++) pb[j] = Wc2[(size_t)(8 * j) * ldw];
        }
        const ulonglong2* As2 = (const ulonglong2*)As;
        const ulonglong2* Bs2 = (const ulonglong2*)Bs;
#pragma unroll 8
        for (int k = 0; k < KC; k++) {
            ulonglong2 bv = Bs2[k * 16 + bi];
            ulonglong2 a01 = As2[k * 32 + ai];
            ulonglong2 a23 = As2[k * 32 + ai + 1];
            acc[0] = fma2(a01.x, bv.x, acc[0]);
            acc[1] = fma2(a01.x, bv.y, acc[1]);
            acc[2] = fma2(a01.y, bv.x, acc[2]);
            acc[3] = fma2(a01.y, bv.y, acc[3]);
            acc[4] = fma2(a23.x, bv.x, acc[4]);
            acc[5] = fma2(a23.x, bv.y, acc[5]);
            acc[6] = fma2(a23.y, bv.x, acc[6]);
            acc[7] = fma2(a23.y, bv.y, acc[7]);
        }
        __syncthreads();
        if (++ch == nc) break;
    }
}

__device__ __forceinline__ void store_tile_raw(float* out, int ldo, int c0,
                                               const unsigned long long acc[8]) {
    int tid = threadIdx.x;
    int m8 = (tid >> 4) * 8, n2 = (tid & 15) * 2;
#pragma unroll
    for (int mp = 0; mp < 4; mp++)
#pragma unroll
        for (int nn = 0; nn < 2; nn++) {
            float2 v = unpack2(acc[mp * 2 + nn]);
            int r = m8 + 2 * mp, c = c0 + n2 + nn;
            out[(size_t)r * ldo + c] = v.x;
            out[(size_t)(r + 1) * ldo + c] = v.y;
        }
}

// ---------------- init: mean_enc, WfcT, lstmb, embW, flags ----------------
__global__ void k_init(const float* __restrict__ enc, const float* __restrict__ Wfc,
                       const float* __restrict__ bih, const float* __restrict__ bhh,
                       const float* __restrict__ emb, const float* __restrict__ Wih) {
    __shared__ float es[NE];
    int bx = blockIdx.x, tid = threadIdx.x;  // 512 threads
    if (bx < NB) {
        const float* eb = enc + (size_t)bx * NP * NENC + tid;
        float s0 = 0.f, s1 = 0.f, s2 = 0.f, s3 = 0.f, s4 = 0.f;
#pragma unroll 5
        for (int p = 0; p < NP; p += 5) {
            s0 += eb[(size_t)(p + 0) * NENC];
            s1 += eb[(size_t)(p + 1) * NENC];
            s2 += eb[(size_t)(p + 2) * NENC];
            s3 += eb[(size_t)(p + 3) * NENC];
            s4 += eb[(size_t)(p + 4) * NENC];
        }
        g_mean[bx * NENC + tid] = (((s0 + s1) + (s2 + s3)) + s4) / 625.0f;
        if (tid == 0) {
            g_rowval[bx] = -INFINITY;
            g_rowflat[bx] = 0;
            g_tok[bx] = START_TOK;
        }
        if (bx == 0 && tid == 0) g_done[0] = 0;
    } else if (bx < NB + NV) {
        int col = bx - NB;
        g_WfcT[col * NH + tid] = Wfc[tid * NV + col];
    } else if (bx < NB + NV + 4) {
        int j = (bx - NB - NV) * 512 + tid;
        g_lstmb[j] = bih[j] + bhh[j];
    } else {
        int idx = bx - (NB + NV + 4);
        int t = idx >> 2, seg = idx & 3;
        if (tid < NE) es[tid] = emb[t * NE + tid];
        __syncthreads();
        int col = seg * 512 + tid;
        float acc = 0.f;
#pragma unroll 8
        for (int k = 0; k < NE; k++) acc = fmaf(es[k], Wih[(size_t)k * NG + col], acc);
        g_embW[t * NG + col] = acc;
    }
}

// ---------------- att1 = enc @ We + be  +  h0/c0 (merged) ----------------
__global__ __launch_bounds__(256) void k_att1(const float* __restrict__ enc,
                                              const float* __restrict__ We,
                                              const float* __restrict__ be,
                                              const float* __restrict__ Wh0,
                                              const float* __restrict__ bh0,
                                              const float* __restrict__ Wc0,
                                              const float* __restrict__ bc0) {
    __shared__ __align__(16) float As[KC * 128];
    __shared__ __align__(16) float2 Bs[KC * 32];
    int bx = blockIdx.x, tid = threadIdx.x;
    unsigned long long acc[8];
    int m8 = (tid >> 4) * 8, n2 = (tid & 15) * 2;
    if (bx < 5000) {
        int mt = bx >> 3, c0 = (bx & 7) * 32;
        gemm128x32(enc + (size_t)mt * 128 * NENC, NENC, We, NA, c0, NENC, acc, As, Bs);
        float* out = g_att1 + (size_t)mt * 128 * NA;
#pragma unroll
        for (int mp = 0; mp < 4; mp++)
#pragma unroll
            for (int nn = 0; nn < 2; nn++) {
                float2 v = unpack2(acc[mp * 2 + nn]);
                int r = m8 + 2 * mp, c = c0 + n2 + nn;
                out[(size_t)r * NA + c] = v.x + be[c];
                out[(size_t)(r + 1) * NA + c] = v.y + be[c];
            }
    } else {
        int b2 = bx - 5000;
        const float* W = (b2 < 16) ? Wh0 : Wc0;
        const float* bias = (b2 < 16) ? bh0 : bc0;
        float* out = (b2 < 16) ? g_h : g_c;
        int c0 = (b2 & 15) * 32;
        gemm128x32(g_mean, NENC, W, NH, c0, NENC, acc, As, Bs);
#pragma unroll
        for (int mp = 0; mp < 4; mp++)
#pragma unroll
            for (int nn = 0; nn < 2; nn++) {
                float2 v = unpack2(acc[mp * 2 + nn]);
                int r = m8 + 2 * mp, c = c0 + n2 + nn;
                out[r * NH + c] = v.x + bias[c];
                out[(r + 1) * NH + c] = v.y + bias[c];
            }
    }
}

// ---------------- K1: all h-GEMMs (att2 x32, Whh x128, Wb x64) + done-flag ----------------
__global__ __launch_bounds__(256, 2) void k_gemms(const float* __restrict__ Wd,
                                                  const float* __restrict__ Whh,
                                                  const float* __restrict__ Wb) {
    __shared__ __align__(16) float As[KC * 128];
    __shared__ __align__(16) float2 Bs[KC * 32];
    int bx = blockIdx.x, tid = threadIdx.x;
    if (bx == 0) {  // done flag from previous step's row argmaxes
        float* dv = As;
        int* dfi = (int*)(As + 192);
        if (tid < 128) {
            dv[tid] = g_rowval[tid];
            dfi[tid] = g_rowflat[tid];
        }
        __syncthreads();
        for (int s = 64; s > 0; s >>= 1) {
            if (tid < s) {
                float ov = dv[tid + s];
                int of = dfi[tid + s];
                if (ov > dv[tid] || (ov == dv[tid] && of < dfi[tid])) {
                    dv[tid] = ov;
                    dfi[tid] = of;
                }
            }
            __syncthreads();
        }
        if (tid == 0 && dfi[0] == END_TOK) g_done[0] = 1;
        __syncthreads();
    }
    unsigned long long acc[8];
    if (bx < 32) {  // att2 partials: 8 tiles x 4 K-splits
        int ks = bx & 3, tile = bx >> 2;
        gemm128x32(g_h + ks * 128, NH, Wd + (size_t)(ks * 128) * NA, NA, tile * 32, 128, acc, As,
                   Bs);
        store_tile_raw(g_a2p[ks], NA, tile * 32, acc);
    } else if (bx < 160) {  // Whh: 64 col-tiles x 2 K-splits
        int idx = bx - 32;
        int ks = idx & 1, tile = idx >> 1;
        gemm128x32(g_h + ks * 256, NH, Whh + (size_t)(ks * 256) * NG, NG, tile * 32, 256, acc, As,
                   Bs);
        store_tile_raw(g_gw[ks], NG, tile * 32, acc);
    } else {  // Wb gate partials: 16 tiles x 4 K-splits
        int idx = bx - 160;
        int ks = idx & 3, tile = idx >> 2;
        gemm128x32(g_h + ks * 128, NH, Wb + (size_t)(ks * 128) * NENC, NENC, tile * 32, 128, acc,
                   As, Bs);
        store_tile_raw(g_gtp[ks], NENC, tile * 32, acc);
    }
}

// ---------------- K2: pure e-pass, 640 blocks (128 b x 5 chunks of 125 p) ----------------
// Layout: 4 lanes per p; lane covers a-range [j*16 + sub*4, +4) over 16 unrolled LDG.128.
__global__ __launch_bounds__(256) void k_epass(const float* __restrict__ wf,
                                               const float* __restrict__ bd) {
    __shared__ __align__(16) float att2s[NA];
    __shared__ __align__(16) float wfs[NA];
    int bx = blockIdx.x, tid = threadIdx.x;
    int b = bx / 5, chunk = bx - b * 5;
    int pstart = chunk * 125;
    att2s[tid] = g_a2p[0][b * NA + tid] + g_a2p[1][b * NA + tid] + g_a2p[2][b * NA + tid] +
                 g_a2p[3][b * NA + tid] + bd[tid];
    wfs[tid] = wf[tid];
    __syncthreads();
    int wid = tid >> 5, lane = tid & 31;
    int sub = lane & 3, pofs = lane >> 2;  // 4 lanes per p, 8 p's per warp
    const float* base = g_att1 + (size_t)b * NP * NA;
    const float4* a4 = (const float4*)att2s + sub;
    const float4* w4 = (const float4*)wfs + sub;
#pragma unroll
    for (int pass = 0; pass < 2; pass++) {
        int rel = pass * 64 + wid * 8 + pofs;
        int p = pstart + rel;
        bool ok = rel < 125;
        float s = 0.f;
        if (ok) {
            const float4* ptr = (const float4*)(base + (size_t)p * NA) + sub;
#pragma unroll
            for (int j = 0; j < 16; j++) {
                float4 v = ptr[j * 4];
                float4 a = a4[j * 4];
                float4 w = w4[j * 4];
                s += fmaxf(v.x + a.x, 0.f) * w.x + fmaxf(v.y + a.y, 0.f) * w.y +
                     fmaxf(v.z + a.z, 0.f) * w.z + fmaxf(v.w + a.w, 0.f) * w.w;
            }
        }
        s += __shfl_xor_sync(0xffffffffu, s, 1);
        s += __shfl_xor_sync(0xffffffffu, s, 2);
        if (ok && sub == 0) g_e[b * NP + p] = s;
    }
}

// ---------------- K3: softmax (per-block, redundant x4) + awe column-slice + gate ----------------
// 512 blocks = 128 b x 4 enc-column slices of 128. No cross-block combine needed.
__global__ __launch_bounds__(256) void k_awe(const float* __restrict__ enc,
                                             const float* __restrict__ bb) {
    int bx = blockIdx.x, tid = threadIdx.x;
    int b = bx >> 2, sl = bx & 3;
    __shared__ float es[NP];
    __shared__ float red[256];
    __shared__ __align__(16) float2 part[3][64];
    for (int i = tid; i < NP; i += 256) es[i] = g_e[b * NP + i];
    __syncthreads();
    float m = -INFINITY;
    for (int i = tid; i < NP; i += 256) m = fmaxf(m, es[i]);
    red[tid] = m;
    __syncthreads();
    for (int s2 = 128; s2 > 0; s2 >>= 1) {
        if (tid < s2) red[tid] = fmaxf(red[tid], red[tid + s2]);
        __syncthreads();
    }
    float M = red[0];
    __syncthreads();
    float sum = 0.f;
    for (int i = tid; i < NP; i += 256) {
        float v = expf(es[i] - M);
        es[i] = v;
        sum += v;
    }
    red[tid] = sum;
    __syncthreads();
    for (int s2 = 128; s2 > 0; s2 >>= 1) {
        if (tid < s2) red[tid] += red[tid + s2];
        __syncthreads();
    }
    float inv = 1.f / red[0];
    __syncthreads();
    for (int i = tid; i < NP; i += 256) es[i] *= inv;
    __syncthreads();
    // awe slice: thread owns float2 at col, 4 p-groups stride 4
    int cq = tid & 63, pg = tid >> 6;
    int col = sl * 128 + cq * 2;
    const float* eb = enc + (size_t)b * NP * NENC + col;
    float2 acc = make_float2(0.f, 0.f);
#pragma unroll 8
    for (int p = pg; p < NP; p += 4) {
        float a = es[p];
        float2 l = *(const float2*)(eb + (size_t)p * NENC);
        acc.x += a * l.x;
        acc.y += a * l.y;
    }
    if (pg > 0) part[pg - 1][cq] = acc;
    __syncthreads();
    if (pg == 0) {
        float2 p1 = part[0][cq], p2 = part[1][cq], p3 = part[2][cq];
        acc.x += p1.x + p2.x + p3.x;
        acc.y += p1.y + p2.y + p3.y;
        float2 g0 = *(const float2*)(g_gtp[0] + b * NENC + col);
        float2 g1 = *(const float2*)(g_gtp[1] + b * NENC + col);
        float2 g2 = *(const float2*)(g_gtp[2] + b * NENC + col);
        float2 g3 = *(const float2*)(g_gtp[3] + b * NENC + col);
        float2 bbv = *(const float2*)(bb + col);
        float gx = sigmoidf_(g0.x + g1.x + g2.x + g3.x + bbv.x);
        float gy = sigmoidf_(g0.y + g1.y + g2.y + g3.y + bbv.y);
        *(float2*)(g_x + b * NH + col) = make_float2(acc.x * gx, acc.y * gy);
    }
}

// ---------------- K4: awe @ Wih[256:768]  (64 col-tiles x 2 K-splits) ----------------
__global__ __launch_bounds__(256, 2) void k_wih(const float* __restrict__ Wih) {
    __shared__ __align__(16) float As[KC * 128];
    __shared__ __align__(16) float2 Bs[KC * 32];
    int bx = blockIdx.x;
    int ks = bx & 1, tile = bx >> 1;
    unsigned long long acc[8];
    gemm128x32(g_x + ks * 256, NH, Wih + (size_t)(NE + ks * 256) * NG, NG, tile * 32, 256, acc,
               As, Bs);
    store_tile_raw(g_wp[ks], NG, tile * 32, acc);
}

// ---------------- K5: gate-sum + LSTM + preds + argmax + token feedback ----------------
__global__ __launch_bounds__(512) void k_step(const float* __restrict__ bfc,
                                              float* __restrict__ out, int t) {
    int b = blockIdx.x, tid = threadIdx.x, wid = tid >> 5, lane = tid & 31;
    __shared__ __align__(16) float hs[NH];
    __shared__ float pv[128];
    __shared__ int pi_[128];
    int tok = g_tok[b];
    {
        int j = tid;
        const float* w0 = g_gw[0] + b * NG;
        const float* w1 = g_gw[1] + b * NG;
        const float* p0 = g_wp[0] + b * NG;
        const float* p1 = g_wp[1] + b * NG;
        const float* ew = g_embW + tok * NG;
        float iv = w0[j] + w1[j] + p0[j] + p1[j] + ew[j] + g_lstmb[j];
        float fv = w0[j + 512] + w1[j + 512] + p0[j + 512] + p1[j + 512] + ew[j + 512] +
                   g_lstmb[j + 512];
        float gv = w0[j + 1024] + w1[j + 1024] + p0[j + 1024] + p1[j + 1024] + ew[j + 1024] +
                   g_lstmb[j + 1024];
        float ov = w0[j + 1536] + w1[j + 1536] + p0[j + 1536] + p1[j + 1536] + ew[j + 1536] +
                   g_lstmb[j + 1536];
        float c = g_c[b * NH + j];
        float cn = sigmoidf_(fv) * c + sigmoidf_(iv) * tanhf(gv);
        float hn = sigmoidf_(ov) * tanhf(cn);
        g_c[b * NH + j] = cn;
        g_h[b * NH + j] = hn;
        hs[j] = hn;
    }
    if (tid < 128) {
        pv[tid] = -INFINITY;
        pi_[tid] = tid;
    }
    __syncthreads();
    int done = g_done[0];
    const float4* hs4 = (const float4*)hs;
    for (int col = wid; col < NV; col += 16) {
        const float4* wr = (const float4*)(g_WfcT + col * NH);
        float s = 0.f;
#pragma unroll
        for (int i = 0; i < 4; i++) {
            float4 h4 = hs4[lane + 32 * i];
            float4 w4 = wr[lane + 32 * i];
            s += h4.x * w4.x + h4.y * w4.y + h4.z * w4.z + h4.w * w4.w;
        }
#pragma unroll
        for (int o = 16; o > 0; o >>= 1) s += __shfl_down_sync(0xffffffffu, s, o);
        if (lane == 0) {
            s += bfc[col];
            out[(size_t)b * NT * NV + (size_t)t * NV + col] = done ? 0.f : s;
            pv[col] = s;
            pi_[col] = col;
        }
    }
    __syncthreads();
    for (int s2 = 64; s2 > 0; s2 >>= 1) {
        if (tid < s2) {
            float ov = pv[tid + s2];
            int oi = pi_[tid + s2];
            if (ov > pv[tid] || (ov == pv[tid] && oi < pi_[tid])) {
                pv[tid] = ov;
                pi_[tid] = oi;
            }
        }
        __syncthreads();
    }
    if (tid == 0) {
        g_rowval[b] = pv[0];
        g_rowflat[b] = b * NV + pi_[0];
        g_tok[b] = pi_[0];
    }
}

extern "C" void kernel_launch(void* const* d_in, const int* in_sizes, int n_in,
                              void* d_out, int out_size) {
    (void)in_sizes; (void)n_in; (void)out_size;
    const float* enc = (const float*)d_in[0];
    const float* emb = (const float*)d_in[1];
    const float* We  = (const float*)d_in[2];
    const float* be  = (const float*)d_in[3];
    const float* Wd  = (const float*)d_in[4];
    const float* bd  = (const float*)d_in[5];
    const float* wf  = (const float*)d_in[6];
    const float* Wh0 = (const float*)d_in[8];
    const float* bh0 = (const float*)d_in[9];
    const float* Wc0 = (const float*)d_in[10];
    const float* bc0 = (const float*)d_in[11];
    const float* Wb  = (const float*)d_in[12];
    const float* bb  = (const float*)d_in[13];
    const float* Wih = (const float*)d_in[14];
    const float* Whh = (const float*)d_in[15];
    const float* bih = (const float*)d_in[16];
    const float* bhh = (const float*)d_in[17];
    const float* Wfc = (const float*)d_in[18];
    const float* bfc = (const float*)d_in[19];
    float* out = (float*)d_out;

    k_init<<<NB + NV + 4 + NV * 4, 512>>>(enc, Wfc, bih, bhh, emb, Wih);
    k_att1<<<5032, 256>>>(enc, We, be, Wh0, bh0, Wc0, bc0);
    for (int t = 0; t < NT; t++) {
        k_gemms<<<224, 256>>>(Wd, Whh, Wb);
        k_epass<<<640, 256>>>(wf, bd);
        k_awe<<<512, 256>>>(enc, bb);
        k_wih<<<128, 256>>>(Wih);
        k_step<<<NB, 512>>>(bfc, out, t);
    }
}

// round 10
// speedup vs baseline: 1.0486x; 1.0486x over previous
#include <cuda_runtime.h>
#include <math.h>

#define NB 128
#define NP 625
#define NENC 512
#define NA 256
#define NE 256
#define NH 512
#define NV 70
#define NT 70
#define NG 2048
#define KC 64
#define START_TOK 68
#define END_TOK 69

// ---------------- scratch ----------------
__device__ float g_att1[NB * NP * NA];   // 81.92MB
__device__ float g_h[NB * NH];
__device__ float g_c[NB * NH];
__device__ float g_mean[NB * NENC];
__device__ float g_x[NB * NH];           // gated awe
__device__ float g_e[NB * NP];           // energies -> (in-place) alpha
__device__ float g_a2p[4][NB * NA];      // att2 K-partials
__device__ float g_gtp[4][NB * NENC];    // gate  K-partials
__device__ float g_gw[2][NB * NG];       // h@Whh K-partials
__device__ float g_wp[2][NB * NG];       // awe@Wih2 K-partials
__device__ float g_embW[NV * NG];        // emb @ Wih[0:256] per vocab token
__device__ float g_lstmb[NG];            // bih + bhh
__device__ float g_WfcT[NV * NH];
__device__ float g_rowval[NB];
__device__ int   g_rowflat[NB];
__device__ int   g_tok[NB];
__device__ int   g_cnt[NB];
__device__ int   g_done[1];

// ---------------- f32x2 helpers ----------------
__device__ __forceinline__ unsigned long long fma2(unsigned long long a, unsigned long long b,
                                                   unsigned long long c) {
    unsigned long long d;
    asm("fma.rn.f32x2 %0, %1, %2, %3;" : "=l"(d) : "l"(a), "l"(b), "l"(c));
    return d;
}
__device__ __forceinline__ float2 unpack2(unsigned long long v) {
    float2 r;
    asm("mov.b64 {%0, %1}, %2;" : "=f"(r.x), "=f"(r.y) : "l"(v));
    return r;
}
__device__ __forceinline__ float sigmoidf_(float x) { return 1.f / (1.f + expf(-x)); }

// ---------------- core GEMM tile: C[128, c0:c0+32] = A[128,K] @ W[K, ldw] ----------------
__device__ __forceinline__ void gemm128x32(const float* __restrict__ A, int lda,
                                           const float* __restrict__ W, int ldw, int c0, int K,
                                           unsigned long long acc[8], float* As, float2* Bs) {
    const int tid = threadIdx.x;
    const int ai = (tid >> 4) * 2;
    const int bi = tid & 15;
    const int la_m = tid & 127, la_k = (tid >> 7) * 32;
    const int lb_n = tid & 31, lb_k = tid >> 5;
#pragma unroll
    for (int j = 0; j < 8; j++) acc[j] = 0ULL;
    float4 pa[8];
    float pb[8];
    const float* Arow = A + (size_t)la_m * lda + la_k;
    const float* Wcol = W + (size_t)lb_k * ldw + c0 + lb_n;
#pragma unroll
    for (int j = 0; j < 8; j++) pa[j] = *(const float4*)(Arow + 4 * j);
#pragma unroll
    for (int j = 0; j < 8; j++) pb[j] = Wcol[(size_t)(8 * j) * ldw];
    const int nc = K / KC;
    for (int ch = 0;;) {
#pragma unroll
        for (int j = 0; j < 8; j++) {
            float4 v = pa[j];
            int kk = la_k + 4 * j;
            As[(kk + 0) * 128 + la_m] = v.x;
            As[(kk + 1) * 128 + la_m] = v.y;
            As[(kk + 2) * 128 + la_m] = v.z;
            As[(kk + 3) * 128 + la_m] = v.w;
        }
#pragma unroll
        for (int j = 0; j < 8; j++) Bs[(lb_k + 8 * j) * 32 + lb_n] = make_float2(pb[j], pb[j]);
        __syncthreads();
        if (ch + 1 < nc) {
            const float* Ar2 = Arow + (ch + 1) * KC;
            const float* Wc2 = Wcol + (size_t)((ch + 1) * KC) * ldw;
#pragma unroll
            for (int j = 0; j < 8; j++) pa[j] = *(const float4*)(Ar2 + 4 * j);
#pragma unroll
            for (int j = 0; j < 8; j++) pb[j] = Wc2[(size_t)(8 * j) * ldw];
        }
        const ulonglong2* As2 = (const ulonglong2*)As;
        const ulonglong2* Bs2 = (const ulonglong2*)Bs;
#pragma unroll 8
        for (int k = 0; k < KC; k++) {
            ulonglong2 bv = Bs2[k * 16 + bi];
            ulonglong2 a01 = As2[k * 32 + ai];
            ulonglong2 a23 = As2[k * 32 + ai + 1];
            acc[0] = fma2(a01.x, bv.x, acc[0]);
            acc[1] = fma2(a01.x, bv.y, acc[1]);
            acc[2] = fma2(a01.y, bv.x, acc[2]);
            acc[3] = fma2(a01.y, bv.y, acc[3]);
            acc[4] = fma2(a23.x, bv.x, acc[4]);
            acc[5] = fma2(a23.x, bv.y, acc[5]);
            acc[6] = fma2(a23.y, bv.x, acc[6]);
            acc[7] = fma2(a23.y, bv.y, acc[7]);
        }
        __syncthreads();
        if (++ch == nc) break;
    }
}

__device__ __forceinline__ void store_tile_raw(float* out, int ldo, int c0,
                                               const unsigned long long acc[8]) {
    int tid = threadIdx.x;
    int m8 = (tid >> 4) * 8, n2 = (tid & 15) * 2;
#pragma unroll
    for (int mp = 0; mp < 4; mp++)
#pragma unroll
        for (int nn = 0; nn < 2; nn++) {
            float2 v = unpack2(acc[mp * 2 + nn]);
            int r = m8 + 2 * mp, c = c0 + n2 + nn;
            out[(size_t)r * ldo + c] = v.x;
            out[(size_t)(r + 1) * ldo + c] = v.y;
        }
}

// ---------------- init: mean_enc, WfcT, lstmb, embW, flags ----------------
__global__ void k_init(const float* __restrict__ enc, const float* __restrict__ Wfc,
                       const float* __restrict__ bih, const float* __restrict__ bhh,
                       const float* __restrict__ emb, const float* __restrict__ Wih) {
    __shared__ float es[NE];
    int bx = blockIdx.x, tid = threadIdx.x;  // 512 threads
    if (bx < NB) {
        const float* eb = enc + (size_t)bx * NP * NENC + tid;
        float s0 = 0.f, s1 = 0.f, s2 = 0.f, s3 = 0.f, s4 = 0.f;
#pragma unroll 5
        for (int p = 0; p < NP; p += 5) {
            s0 += eb[(size_t)(p + 0) * NENC];
            s1 += eb[(size_t)(p + 1) * NENC];
            s2 += eb[(size_t)(p + 2) * NENC];
            s3 += eb[(size_t)(p + 3) * NENC];
            s4 += eb[(size_t)(p + 4) * NENC];
        }
        g_mean[bx * NENC + tid] = (((s0 + s1) + (s2 + s3)) + s4) / 625.0f;
        if (tid == 0) {
            g_rowval[bx] = -INFINITY;
            g_rowflat[bx] = 0;
            g_tok[bx] = START_TOK;
            g_cnt[bx] = 0;
        }
        if (bx == 0 && tid == 0) g_done[0] = 0;
    } else if (bx < NB + NV) {
        int col = bx - NB;
        g_WfcT[col * NH + tid] = Wfc[tid * NV + col];
    } else if (bx < NB + NV + 4) {
        int j = (bx - NB - NV) * 512 + tid;
        g_lstmb[j] = bih[j] + bhh[j];
    } else {
        int idx = bx - (NB + NV + 4);
        int t = idx >> 2, seg = idx & 3;
        if (tid < NE) es[tid] = emb[t * NE + tid];
        __syncthreads();
        int col = seg * 512 + tid;
        float acc = 0.f;
#pragma unroll 8
        for (int k = 0; k < NE; k++) acc = fmaf(es[k], Wih[(size_t)k * NG + col], acc);
        g_embW[t * NG + col] = acc;
    }
}

// ---------------- att1 = enc @ We + be  +  h0/c0 (merged) ----------------
__global__ __launch_bounds__(256) void k_att1(const float* __restrict__ enc,
                                              const float* __restrict__ We,
                                              const float* __restrict__ be,
                                              const float* __restrict__ Wh0,
                                              const float* __restrict__ bh0,
                                              const float* __restrict__ Wc0,
                                              const float* __restrict__ bc0) {
    __shared__ __align__(16) float As[KC * 128];
    __shared__ __align__(16) float2 Bs[KC * 32];
    int bx = blockIdx.x, tid = threadIdx.x;
    unsigned long long acc[8];
    int m8 = (tid >> 4) * 8, n2 = (tid & 15) * 2;
    if (bx < 5000) {
        int mt = bx >> 3, c0 = (bx & 7) * 32;
        gemm128x32(enc + (size_t)mt * 128 * NENC, NENC, We, NA, c0, NENC, acc, As, Bs);
        float* out = g_att1 + (size_t)mt * 128 * NA;
#pragma unroll
        for (int mp = 0; mp < 4; mp++)
#pragma unroll
            for (int nn = 0; nn < 2; nn++) {
                float2 v = unpack2(acc[mp * 2 + nn]);
                int r = m8 + 2 * mp, c = c0 + n2 + nn;
                out[(size_t)r * NA + c] = v.x + be[c];
                out[(size_t)(r + 1) * NA + c] = v.y + be[c];
            }
    } else {
        int b2 = bx - 5000;
        const float* W = (b2 < 16) ? Wh0 : Wc0;
        const float* bias = (b2 < 16) ? bh0 : bc0;
        float* out = (b2 < 16) ? g_h : g_c;
        int c0 = (b2 & 15) * 32;
        gemm128x32(g_mean, NENC, W, NH, c0, NENC, acc, As, Bs);
#pragma unroll
        for (int mp = 0; mp < 4; mp++)
#pragma unroll
            for (int nn = 0; nn < 2; nn++) {
                float2 v = unpack2(acc[mp * 2 + nn]);
                int r = m8 + 2 * mp, c = c0 + n2 + nn;
                out[r * NH + c] = v.x + bias[c];
                out[(r + 1) * NH + c] = v.y + bias[c];
            }
    }
}

// ---------------- K1: all h-GEMMs (att2 x32, Whh x128, Wb x64) + done-flag ----------------
__global__ __launch_bounds__(256, 2) void k_gemms(const float* __restrict__ Wd,
                                                  const float* __restrict__ Whh,
                                                  const float* __restrict__ Wb) {
    __shared__ __align__(16) float As[KC * 128];
    __shared__ __align__(16) float2 Bs[KC * 32];
    int bx = blockIdx.x, tid = threadIdx.x;
    if (bx == 0) {  // done flag from previous step's row argmaxes
        float* dv = As;
        int* dfi = (int*)(As + 192);
        if (tid < 128) {
            dv[tid] = g_rowval[tid];
            dfi[tid] = g_rowflat[tid];
        }
        __syncthreads();
        for (int s = 64; s > 0; s >>= 1) {
            if (tid < s) {
                float ov = dv[tid + s];
                int of = dfi[tid + s];
                if (ov > dv[tid] || (ov == dv[tid] && of < dfi[tid])) {
                    dv[tid] = ov;
                    dfi[tid] = of;
                }
            }
            __syncthreads();
        }
        if (tid == 0 && dfi[0] == END_TOK) g_done[0] = 1;
        __syncthreads();
    }
    unsigned long long acc[8];
    if (bx < 32) {  // att2 partials: 8 tiles x 4 K-splits
        int ks = bx & 3, tile = bx >> 2;
        gemm128x32(g_h + ks * 128, NH, Wd + (size_t)(ks * 128) * NA, NA, tile * 32, 128, acc, As,
                   Bs);
        store_tile_raw(g_a2p[ks], NA, tile * 32, acc);
    } else if (bx < 160) {  // Whh: 64 col-tiles x 2 K-splits
        int idx = bx - 32;
        int ks = idx & 1, tile = idx >> 1;
        gemm128x32(g_h + ks * 256, NH, Whh + (size_t)(ks * 256) * NG, NG, tile * 32, 256, acc, As,
                   Bs);
        store_tile_raw(g_gw[ks], NG, tile * 32, acc);
    } else {  // Wb gate partials: 16 tiles x 4 K-splits
        int idx = bx - 160;
        int ks = idx & 3, tile = idx >> 2;
        gemm128x32(g_h + ks * 128, NH, Wb + (size_t)(ks * 128) * NENC, NENC, tile * 32, 128, acc,
                   As, Bs);
        store_tile_raw(g_gtp[ks], NENC, tile * 32, acc);
    }
}

// ---------------- K2: e-pass (16 lanes/p, low regs) + fused per-b softmax (last block) ----------------
__global__ __launch_bounds__(256) void k_epass(const float* __restrict__ wf,
                                               const float* __restrict__ bd) {
    __shared__ __align__(16) float att2s[NA];
    __shared__ __align__(16) float wfs[NA];
    __shared__ float red[256];
    __shared__ int lastf;
    int bx = blockIdx.x, tid = threadIdx.x;
    int b = bx / 5, chunk = bx - b * 5;
    int pstart = chunk * 125;
    att2s[tid] = g_a2p[0][b * NA + tid] + g_a2p[1][b * NA + tid] + g_a2p[2][b * NA + tid] +
                 g_a2p[3][b * NA + tid] + bd[tid];
    wfs[tid] = wf[tid];
    __syncthreads();
    int wid = tid >> 5, lane = tid & 31;
    int sub = lane & 15, pofs = lane >> 4;  // 16 lanes per p, 2 p's per warp/iter
    const float* base = g_att1 + (size_t)b * NP * NA;
    float4 a[4], w[4];
#pragma unroll
    for (int j = 0; j < 4; j++) {
        a[j] = ((const float4*)att2s)[sub * 4 + j];
        w[j] = ((const float4*)wfs)[sub * 4 + j];
    }
#pragma unroll 2
    for (int it = 0; it < 8; it++) {
        int rel = it * 16 + wid * 2 + pofs;
        bool ok = rel < 125;
        int p = pstart + (ok ? rel : 0);
        const float4* ptr = (const float4*)(base + (size_t)p * NA) + sub * 4;
        float4 v0 = ptr[0], v1 = ptr[1], v2 = ptr[2], v3 = ptr[3];
        float s = fmaxf(v0.x + a[0].x, 0.f) * w[0].x + fmaxf(v0.y + a[0].y, 0.f) * w[0].y +
                  fmaxf(v0.z + a[0].z, 0.f) * w[0].z + fmaxf(v0.w + a[0].w, 0.f) * w[0].w;
        s += fmaxf(v1.x + a[1].x, 0.f) * w[1].x + fmaxf(v1.y + a[1].y, 0.f) * w[1].y +
             fmaxf(v1.z + a[1].z, 0.f) * w[1].z + fmaxf(v1.w + a[1].w, 0.f) * w[1].w;
        s += fmaxf(v2.x + a[2].x, 0.f) * w[2].x + fmaxf(v2.y + a[2].y, 0.f) * w[2].y +
             fmaxf(v2.z + a[2].z, 0.f) * w[2].z + fmaxf(v2.w + a[2].w, 0.f) * w[2].w;
        s += fmaxf(v3.x + a[3].x, 0.f) * w[3].x + fmaxf(v3.y + a[3].y, 0.f) * w[3].y +
             fmaxf(v3.z + a[3].z, 0.f) * w[3].z + fmaxf(v3.w + a[3].w, 0.f) * w[3].w;
        s += __shfl_xor_sync(0xffffffffu, s, 1);
        s += __shfl_xor_sync(0xffffffffu, s, 2);
        s += __shfl_xor_sync(0xffffffffu, s, 4);
        s += __shfl_xor_sync(0xffffffffu, s, 8);
        if (ok && sub == 0) g_e[b * NP + pstart + rel] = s;
    }
    // ---- last-block-per-b softmax ----
    __syncthreads();
    __threadfence();
    if (tid == 0) {
        int old = atomicAdd(&g_cnt[b], 1);
        lastf = (old == 4);
    }
    __syncthreads();
    if (!lastf) return;
    __threadfence();
    float m = -INFINITY;
    float ev[3];
#pragma unroll
    for (int r = 0; r < 3; r++) {
        int i = tid + r * 256;
        ev[r] = (i < NP) ? g_e[b * NP + i] : -INFINITY;
        m = fmaxf(m, ev[r]);
    }
    red[tid] = m;
    __syncthreads();
    for (int s2 = 128; s2 > 0; s2 >>= 1) {
        if (tid < s2) red[tid] = fmaxf(red[tid], red[tid + s2]);
        __syncthreads();
    }
    float M = red[0];
    __syncthreads();
    float sum = 0.f;
#pragma unroll
    for (int r = 0; r < 3; r++) {
        int i = tid + r * 256;
        if (i < NP) {
            ev[r] = expf(ev[r] - M);
            sum += ev[r];
        }
    }
    red[tid] = sum;
    __syncthreads();
    for (int s2 = 128; s2 > 0; s2 >>= 1) {
        if (tid < s2) red[tid] += red[tid + s2];
        __syncthreads();
    }
    float inv = 1.f / red[0];
#pragma unroll
    for (int r = 0; r < 3; r++) {
        int i = tid + r * 256;
        if (i < NP) g_e[b * NP + i] = ev[r] * inv;
    }
    if (tid == 0) g_cnt[b] = 0;  // reset for next step
}

// ---------------- K3: awe column-slice scan + gate (512 blocks = 128 b x 4 slices) ----------------
__global__ __launch_bounds__(256) void k_awe(const float* __restrict__ enc,
                                             const float* __restrict__ bb) {
    int bx = blockIdx.x, tid = threadIdx.x;
    int b = bx >> 2, sl = bx & 3;
    __shared__ float als[NP];
    __shared__ __align__(16) float4 part[7][32];
    for (int i = tid; i < NP; i += 256) als[i] = g_e[b * NP + i];
    __syncthreads();
    int cq = tid & 31, pg = tid >> 5;  // cq: float4 col in slice, pg: 8 p-groups
    const float4* eb = (const float4*)(enc + (size_t)b * NP * NENC) + sl * 32 + cq;
    float4 acc = make_float4(0.f, 0.f, 0.f, 0.f);
#pragma unroll 4
    for (int p = pg; p < NP; p += 8) {
        float a = als[p];
        float4 v = eb[(size_t)p * 128];
        acc.x += a * v.x;
        acc.y += a * v.y;
        acc.z += a * v.z;
        acc.w += a * v.w;
    }
    if (pg > 0) part[pg - 1][cq] = acc;
    __syncthreads();
    if (pg == 0) {
#pragma unroll
        for (int r = 0; r < 7; r++) {
            float4 pv = part[r][cq];
            acc.x += pv.x;
            acc.y += pv.y;
            acc.z += pv.z;
            acc.w += pv.w;
        }
        int col4 = sl * 32 + cq;
        float4 g0 = ((const float4*)(g_gtp[0] + b * NENC))[col4];
        float4 g1 = ((const float4*)(g_gtp[1] + b * NENC))[col4];
        float4 g2 = ((const float4*)(g_gtp[2] + b * NENC))[col4];
        float4 g3 = ((const float4*)(g_gtp[3] + b * NENC))[col4];
        float4 bbv = ((const float4*)bb)[col4];
        float gx = sigmoidf_(g0.x + g1.x + g2.x + g3.x + bbv.x);
        float gy = sigmoidf_(g0.y + g1.y + g2.y + g3.y + bbv.y);
        float gz = sigmoidf_(g0.z + g1.z + g2.z + g3.z + bbv.z);
        float gw = sigmoidf_(g0.w + g1.w + g2.w + g3.w + bbv.w);
        ((float4*)(g_x + b * NH))[col4] =
            make_float4(acc.x * gx, acc.y * gy, acc.z * gz, acc.w * gw);
    }
}

// ---------------- K4: awe @ Wih[256:768]  (64 col-tiles x 2 K-splits) ----------------
__global__ __launch_bounds__(256, 2) void k_wih(const float* __restrict__ Wih) {
    __shared__ __align__(16) float As[KC * 128];
    __shared__ __align__(16) float2 Bs[KC * 32];
    int bx = blockIdx.x;
    int ks = bx & 1, tile = bx >> 1;
    unsigned long long acc[8];
    gemm128x32(g_x + ks * 256, NH, Wih + (size_t)(NE + ks * 256) * NG, NG, tile * 32, 256, acc,
               As, Bs);
    store_tile_raw(g_wp[ks], NG, tile * 32, acc);
}

// ---------------- K5: gate-sum + LSTM + preds + argmax + token feedback ----------------
__global__ __launch_bounds__(512) void k_step(const float* __restrict__ bfc,
                                              float* __restrict__ out, int t) {
    int b = blockIdx.x, tid = threadIdx.x, wid = tid >> 5, lane = tid & 31;
    __shared__ __align__(16) float hs[NH];
    __shared__ float pv[128];
    __shared__ int pi_[128];
    int tok = g_tok[b];
    {
        int j = tid;
        const float* w0 = g_gw[0] + b * NG;
        const float* w1 = g_gw[1] + b * NG;
        const float* p0 = g_wp[0] + b * NG;
        const float* p1 = g_wp[1] + b * NG;
        const float* ew = g_embW + tok * NG;
        float iv = w0[j] + w1[j] + p0[j] + p1[j] + ew[j] + g_lstmb[j];
        float fv = w0[j + 512] + w1[j + 512] + p0[j + 512] + p1[j + 512] + ew[j + 512] +
                   g_lstmb[j + 512];
        float gv = w0[j + 1024] + w1[j + 1024] + p0[j + 1024] + p1[j + 1024] + ew[j + 1024] +
                   g_lstmb[j + 1024];
        float ov = w0[j + 1536] + w1[j + 1536] + p0[j + 1536] + p1[j + 1536] + ew[j + 1536] +
                   g_lstmb[j + 1536];
        float c = g_c[b * NH + j];
        float cn = sigmoidf_(fv) * c + sigmoidf_(iv) * tanhf(gv);
        float hn = sigmoidf_(ov) * tanhf(cn);
        g_c[b * NH + j] = cn;
        g_h[b * NH + j] = hn;
        hs[j] = hn;
    }
    if (tid < 128) {
        pv[tid] = -INFINITY;
        pi_[tid] = tid;
    }
    __syncthreads();
    int done = g_done[0];
    const float4* hs4 = (const float4*)hs;
    for (int col = wid; col < NV; col += 16) {
        const float4* wr = (const float4*)(g_WfcT + col * NH);
        float s = 0.f;
#pragma unroll
        for (int i = 0; i < 4; i++) {
            float4 h4 = hs4[lane + 32 * i];
            float4 w4 = wr[lane + 32 * i];
            s += h4.x * w4.x + h4.y * w4.y + h4.z * w4.z + h4.w * w4.w;
        }
#pragma unroll
        for (int o = 16; o > 0; o >>= 1) s += __shfl_down_sync(0xffffffffu, s, o);
        if (lane == 0) {
            s += bfc[col];
            out[(size_t)b * NT * NV + (size_t)t * NV + col] = done ? 0.f : s;
            pv[col] = s;
            pi_[col] = col;
        }
    }
    __syncthreads();
    for (int s2 = 64; s2 > 0; s2 >>= 1) {
        if (tid < s2) {
            float ov = pv[tid + s2];
            int oi = pi_[tid + s2];
            if (ov > pv[tid] || (ov == pv[tid] && oi < pi_[tid])) {
                pv[tid] = ov;
                pi_[tid] = oi;
            }
        }
        __syncthreads();
    }
    if (tid == 0) {
        g_rowval[b] = pv[0];
        g_rowflat[b] = b * NV + pi_[0];
        g_tok[b] = pi_[0];
    }
}

extern "C" void kernel_launch(void* const* d_in, const int* in_sizes, int n_in,
                              void* d_out, int out_size) {
    (void)in_sizes; (void)n_in; (void)out_size;
    const float* enc = (const float*)d_in[0];
    const float* emb = (const float*)d_in[1];
    const float* We  = (const float*)d_in[2];
    const float* be  = (const float*)d_in[3];
    const float* Wd  = (const float*)d_in[4];
    const float* bd  = (const float*)d_in[5];
    const float* wf  = (const float*)d_in[6];
    const float* Wh0 = (const float*)d_in[8];
    const float* bh0 = (const float*)d_in[9];
    const float* Wc0 = (const float*)d_in[10];
    const float* bc0 = (const float*)d_in[11];
    const float* Wb  = (const float*)d_in[12];
    const float* bb  = (const float*)d_in[13];
    const float* Wih = (const float*)d_in[14];
    const float* Whh = (const float*)d_in[15];
    const float* bih = (const float*)d_in[16];
    const float* bhh = (const float*)d_in[17];
    const float* Wfc = (const float*)d_in[18];
    const float* bfc = (const float*)d_in[19];
    float* out = (float*)d_out;

    k_init<<<NB + NV + 4 + NV * 4, 512>>>(enc, Wfc, bih, bhh, emb, Wih);
    k_att1<<<5032, 256>>>(enc, We, be, Wh0, bh0, Wc0, bc0);
    for (int t = 0; t < NT; t++) {
        k_gemms<<<224, 256>>>(Wd, Whh, Wb);
        k_epass<<<640, 256>>>(wf, bd);
        k_awe<<<512, 256>>>(enc, bb);
        k_wih<<<128, 256>>>(Wih);
        k_step<<<NB, 512>>>(bfc, out, t);
    }
}

// round 12
// speedup vs baseline: 1.1678x; 1.1137x over previous
#include <cuda_runtime.h>
#include <math.h>

#define NB 128
#define NP 625
#define NENC 512
#define NA 256
#define NE 256
#define NH 512
#define NV 70
#define NT 70
#define NG 2048
#define KC 64
#define START_TOK 68
#define END_TOK 69
#define CHK 157  // p-chunk length (last chunk = 154)

// ---------------- scratch ----------------
__device__ float g_att1[NB * NP * NA];   // 81.92MB
__device__ float g_h[NB * NH];
__device__ float g_c[NB * NH];
__device__ float g_mean[NB * NENC];
__device__ float g_x[NB * NH];           // gated awe
__device__ float g_a2p[4][NB * NA];      // att2 K-partials
__device__ float g_gtp[4][NB * NENC];    // gate  K-partials
__device__ float g_xp[4][NB * NENC];     // awe chunk-partials
__device__ float g_gw[4][NB * NG];       // h@Whh K-partials
__device__ float g_wp[4][NB * NG];       // awe@Wih2 K-partials
__device__ float g_embW[NV * NG];        // emb @ Wih[0:256] per vocab token
__device__ float g_lstmb[NG];            // bih + bhh
__device__ float g_WfcT[NV * NH];
__device__ float g_stat[NB * 8];         // per-b, per-chunk (M, S)
__device__ float g_rowval[NB];
__device__ int   g_rowflat[NB];
__device__ int   g_tok[NB];
__device__ int   g_cnt[NB];              // epoch counter (4 per step)
__device__ int   g_done[1];

// ---------------- f32x2 helpers ----------------
__device__ __forceinline__ unsigned long long fma2(unsigned long long a, unsigned long long b,
                                                   unsigned long long c) {
    unsigned long long d;
    asm("fma.rn.f32x2 %0, %1, %2, %3;" : "=l"(d) : "l"(a), "l"(b), "l"(c));
    return d;
}
__device__ __forceinline__ float2 unpack2(unsigned long long v) {
    float2 r;
    asm("mov.b64 {%0, %1}, %2;" : "=f"(r.x), "=f"(r.y) : "l"(v));
    return r;
}
__device__ __forceinline__ float sigmoidf_(float x) { return 1.f / (1.f + expf(-x)); }

// ---------------- core GEMM tile: C[128, c0:c0+32] = A[128,K] @ W[K, ldw] ----------------
__device__ __forceinline__ void gemm128x32(const float* __restrict__ A, int lda,
                                           const float* __restrict__ W, int ldw, int c0, int K,
                                           unsigned long long acc[8], float* As, float2* Bs) {
    const int tid = threadIdx.x;
    const int ai = (tid >> 4) * 2;
    const int bi = tid & 15;
    const int la_m = tid & 127, la_k = (tid >> 7) * 32;
    const int lb_n = tid & 31, lb_k = tid >> 5;
#pragma unroll
    for (int j = 0; j < 8; j++) acc[j] = 0ULL;
    float4 pa[8];
    float pb[8];
    const float* Arow = A + (size_t)la_m * lda + la_k;
    const float* Wcol = W + (size_t)lb_k * ldw + c0 + lb_n;
#pragma unroll
    for (int j = 0; j < 8; j++) pa[j] = *(const float4*)(Arow + 4 * j);
#pragma unroll
    for (int j = 0; j < 8; j++) pb[j] = Wcol[(size_t)(8 * j) * ldw];
    const int nc = K / KC;
    for (int ch = 0;;) {
#pragma unroll
        for (int j = 0; j < 8; j++) {
            float4 v = pa[j];
            int kk = la_k + 4 * j;
            As[(kk + 0) * 128 + la_m] = v.x;
            As[(kk + 1) * 128 + la_m] = v.y;
            As[(kk + 2) * 128 + la_m] = v.z;
            As[(kk + 3) * 128 + la_m] = v.w;
        }
#pragma unroll
        for (int j = 0; j < 8; j++) Bs[(lb_k + 8 * j) * 32 + lb_n] = make_float2(pb[j], pb[j]);
        __syncthreads();
        if (ch + 1 < nc) {
            const float* Ar2 = Arow + (ch + 1) * KC;
            const float* Wc2 = Wcol + (size_t)((ch + 1) * KC) * ldw;
#pragma unroll
            for (int j = 0; j < 8; j++) pa[j] = *(const float4*)(Ar2 + 4 * j);
#pragma unroll
            for (int j = 0; j < 8; j++) pb[j] = Wc2[(size_t)(8 * j) * ldw];
        }
        const ulonglong2* As2 = (const ulonglong2*)As;
        const ulonglong2* Bs2 = (const ulonglong2*)Bs;
#pragma unroll 8
        for (int k = 0; k < KC; k++) {
            ulonglong2 bv = Bs2[k * 16 + bi];
            ulonglong2 a01 = As2[k * 32 + ai];
            ulonglong2 a23 = As2[k * 32 + ai + 1];
            acc[0] = fma2(a01.x, bv.x, acc[0]);
            acc[1] = fma2(a01.x, bv.y, acc[1]);
            acc[2] = fma2(a01.y, bv.x, acc[2]);
            acc[3] = fma2(a01.y, bv.y, acc[3]);
            acc[4] = fma2(a23.x, bv.x, acc[4]);
            acc[5] = fma2(a23.x, bv.y, acc[5]);
            acc[6] = fma2(a23.y, bv.x, acc[6]);
            acc[7] = fma2(a23.y, bv.y, acc[7]);
        }
        __syncthreads();
        if (++ch == nc) break;
    }
}

__device__ __forceinline__ void store_tile_raw(float* out, int ldo, int c0,
                                               const unsigned long long acc[8]) {
    int tid = threadIdx.x;
    int m8 = (tid >> 4) * 8, n2 = (tid & 15) * 2;
#pragma unroll
    for (int mp = 0; mp < 4; mp++)
#pragma unroll
        for (int nn = 0; nn < 2; nn++) {
            float2 v = unpack2(acc[mp * 2 + nn]);
            int r = m8 + 2 * mp, c = c0 + n2 + nn;
            out[(size_t)r * ldo + c] = v.x;
            out[(size_t)(r + 1) * ldo + c] = v.y;
        }
}

// ---------------- init: mean_enc, WfcT, lstmb, embW, flags ----------------
__global__ void k_init(const float* __restrict__ enc, const float* __restrict__ Wfc,
                       const float* __restrict__ bih, const float* __restrict__ bhh,
                       const float* __restrict__ emb, const float* __restrict__ Wih) {
    __shared__ float es[NE];
    int bx = blockIdx.x, tid = threadIdx.x;  // 512 threads
    if (bx < NB) {
        const float* eb = enc + (size_t)bx * NP * NENC + tid;
        float s0 = 0.f, s1 = 0.f, s2 = 0.f, s3 = 0.f, s4 = 0.f;
#pragma unroll 5
        for (int p = 0; p < NP; p += 5) {
            s0 += eb[(size_t)(p + 0) * NENC];
            s1 += eb[(size_t)(p + 1) * NENC];
            s2 += eb[(size_t)(p + 2) * NENC];
            s3 += eb[(size_t)(p + 3) * NENC];
            s4 += eb[(size_t)(p + 4) * NENC];
        }
        g_mean[bx * NENC + tid] = (((s0 + s1) + (s2 + s3)) + s4) / 625.0f;
        if (tid == 0) {
            g_rowval[bx] = -INFINITY;
            g_rowflat[bx] = 0;
            g_tok[bx] = START_TOK;
            g_cnt[bx] = 0;
        }
        if (bx == 0 && tid == 0) g_done[0] = 0;
    } else if (bx < NB + NV) {
        int col = bx - NB;
        g_WfcT[col * NH + tid] = Wfc[tid * NV + col];
    } else if (bx < NB + NV + 4) {
        int j = (bx - NB - NV) * 512 + tid;
        g_lstmb[j] = bih[j] + bhh[j];
    } else {
        int idx = bx - (NB + NV + 4);
        int t = idx >> 2, seg = idx & 3;
        if (tid < NE) es[tid] = emb[t * NE + tid];
        __syncthreads();
        int col = seg * 512 + tid;
        float acc = 0.f;
#pragma unroll 8
        for (int k = 0; k < NE; k++) acc = fmaf(es[k], Wih[(size_t)k * NG + col], acc);
        g_embW[t * NG + col] = acc;
    }
}

// ---------------- att1 = enc @ We + be  +  h0/c0 (merged) ----------------
__global__ __launch_bounds__(256) void k_att1(const float* __restrict__ enc,
                                              const float* __restrict__ We,
                                              const float* __restrict__ be,
                                              const float* __restrict__ Wh0,
                                              const float* __restrict__ bh0,
                                              const float* __restrict__ Wc0,
                                              const float* __restrict__ bc0) {
    __shared__ __align__(16) float As[KC * 128];
    __shared__ __align__(16) float2 Bs[KC * 32];
    int bx = blockIdx.x, tid = threadIdx.x;
    unsigned long long acc[8];
    int m8 = (tid >> 4) * 8, n2 = (tid & 15) * 2;
    if (bx < 5000) {
        int mt = bx >> 3, c0 = (bx & 7) * 32;
        gemm128x32(enc + (size_t)mt * 128 * NENC, NENC, We, NA, c0, NENC, acc, As, Bs);
        float* out = g_att1 + (size_t)mt * 128 * NA;
#pragma unroll
        for (int mp = 0; mp < 4; mp++)
#pragma unroll
            for (int nn = 0; nn < 2; nn++) {
                float2 v = unpack2(acc[mp * 2 + nn]);
                int r = m8 + 2 * mp, c = c0 + n2 + nn;
                out[(size_t)r * NA + c] = v.x + be[c];
                out[(size_t)(r + 1) * NA + c] = v.y + be[c];
            }
    } else {
        int b2 = bx - 5000;
        const float* W = (b2 < 16) ? Wh0 : Wc0;
        const float* bias = (b2 < 16) ? bh0 : bc0;
        float* out = (b2 < 16) ? g_h : g_c;
        int c0 = (b2 & 15) * 32;
        gemm128x32(g_mean, NENC, W, NH, c0, NENC, acc, As, Bs);
#pragma unroll
        for (int mp = 0; mp < 4; mp++)
#pragma unroll
            for (int nn = 0; nn < 2; nn++) {
                float2 v = unpack2(acc[mp * 2 + nn]);
                int r = m8 + 2 * mp, c = c0 + n2 + nn;
                out[r * NH + c] = v.x + bias[c];
                out[(r + 1) * NH + c] = v.y + bias[c];
            }
    }
}

// ---------------- K1: h-GEMMs (att2 x32, Whh x256, Wb x64) + done-flag ----------------
__global__ __launch_bounds__(256, 2) void k_gemms(const float* __restrict__ Wd,
                                                  const float* __restrict__ Whh,
                                                  const float* __restrict__ Wb) {
    __shared__ __align__(16) float As[KC * 128];
    __shared__ __align__(16) float2 Bs[KC * 32];
    int bx = blockIdx.x, tid = threadIdx.x;
    if (bx == 0) {  // done flag from previous step's row argmaxes
        float* dv = As;
        int* dfi = (int*)(As + 192);
        if (tid < 128) {
            dv[tid] = g_rowval[tid];
            dfi[tid] = g_rowflat[tid];
        }
        __syncthreads();
        for (int s = 64; s > 0; s >>= 1) {
            if (tid < s) {
                float ov = dv[tid + s];
                int of = dfi[tid + s];
                if (ov > dv[tid] || (ov == dv[tid] && of < dfi[tid])) {
                    dv[tid] = ov;
                    dfi[tid] = of;
                }
            }
            __syncthreads();
        }
        if (tid == 0 && dfi[0] == END_TOK) g_done[0] = 1;
        __syncthreads();
    }
    unsigned long long acc[8];
    if (bx < 32) {  // att2 partials: 8 tiles x 4 K-splits
        int ks = bx & 3, tile = bx >> 2;
        gemm128x32(g_h + ks * 128, NH, Wd + (size_t)(ks * 128) * NA, NA, tile * 32, 128, acc, As,
                   Bs);
        store_tile_raw(g_a2p[ks], NA, tile * 32, acc);
    } else if (bx < 288) {  // Whh: 64 col-tiles x 4 K-splits
        int idx = bx - 32;
        int ks = idx & 3, tile = idx >> 2;
        gemm128x32(g_h + ks * 128, NH, Whh + (size_t)(ks * 128) * NG, NG, tile * 32, 128, acc, As,
                   Bs);
        store_tile_raw(g_gw[ks], NG, tile * 32, acc);
    } else {  // Wb gate partials: 16 tiles x 4 K-splits
        int idx = bx - 288;
        int ks = idx & 3, tile = idx >> 2;
        gemm128x32(g_h + ks * 128, NH, Wb + (size_t)(ks * 128) * NENC, NENC, tile * 32, 128, acc,
                   As, Bs);
        store_tile_raw(g_gtp[ks], NENC, tile * 32, acc);
    }
}

// ---------------- K2: FUSED e-pass + distributed softmax + awe chunk-scan ----------------
// 512 blocks = 128 b x 4 p-chunks. All blocks co-resident (<=64 regs, ~6KB smem -> 4/SM x 148
// = 592 slots >= 512), so the per-b stats handshake cannot deadlock.
__global__ __launch_bounds__(256, 4) void k_att(const float* __restrict__ enc,
                                                const float* __restrict__ wf,
                                                const float* __restrict__ bd, int t) {
    __shared__ __align__(16) float att2s[NA];
    __shared__ __align__(16) float wfs[NA];
    __shared__ float es[CHK + 3];
    __shared__ float red[256];
    __shared__ __align__(16) float4 part[128];
    int bx = blockIdx.x, tid = threadIdx.x;
    int b = bx >> 2, chunk = bx & 3;
    int pstart = chunk * CHK;
    int len = (chunk < 3) ? CHK : (NP - 3 * CHK);
    att2s[tid] = g_a2p[0][b * NA + tid] + g_a2p[1][b * NA + tid] + g_a2p[2][b * NA + tid] +
                 g_a2p[3][b * NA + tid] + bd[tid];
    wfs[tid] = wf[tid];
    __syncthreads();
    // ---- phase 1: energies for this chunk -> smem ----
    {
        int wid = tid >> 5, lane = tid & 31;
        int sub = lane & 15, pofs = lane >> 4;  // 16 lanes per p
        const float* base = g_att1 + (size_t)b * NP * NA;
        float4 a[4], w[4];
#pragma unroll
        for (int j = 0; j < 4; j++) {
            a[j] = ((const float4*)att2s)[sub * 4 + j];
            w[j] = ((const float4*)wfs)[sub * 4 + j];
        }
#pragma unroll
        for (int it = 0; it < 10; it++) {
            int rel = it * 16 + wid * 2 + pofs;
            int p = pstart + (rel < len ? rel : 0);
            const float4* ptr = (const float4*)(base + (size_t)p * NA) + sub * 4;
            float4 v0 = ptr[0], v1 = ptr[1], v2 = ptr[2], v3 = ptr[3];
            float s = fmaxf(v0.x + a[0].x, 0.f) * w[0].x + fmaxf(v0.y + a[0].y, 0.f) * w[0].y +
                      fmaxf(v0.z + a[0].z, 0.f) * w[0].z + fmaxf(v0.w + a[0].w, 0.f) * w[0].w;
            s += fmaxf(v1.x + a[1].x, 0.f) * w[1].x + fmaxf(v1.y + a[1].y, 0.f) * w[1].y +
                 fmaxf(v1.z + a[1].z, 0.f) * w[1].z + fmaxf(v1.w + a[1].w, 0.f) * w[1].w;
            s += fmaxf(v2.x + a[2].x, 0.f) * w[2].x + fmaxf(v2.y + a[2].y, 0.f) * w[2].y +
                 fmaxf(v2.z + a[2].z, 0.f) * w[2].z + fmaxf(v2.w + a[2].w, 0.f) * w[2].w;
            s += fmaxf(v3.x + a[3].x, 0.f) * w[3].x + fmaxf(v3.y + a[3].y, 0.f) * w[3].y +
                 fmaxf(v3.z + a[3].z, 0.f) * w[3].z + fmaxf(v3.w + a[3].w, 0.f) * w[3].w;
            s += __shfl_xor_sync(0xffffffffu, s, 1);
            s += __shfl_xor_sync(0xffffffffu, s, 2);
            s += __shfl_xor_sync(0xffffffffu, s, 4);
            s += __shfl_xor_sync(0xffffffffu, s, 8);
            if (rel < len && sub == 0) es[rel] = s;
        }
    }
    __syncthreads();
    // ---- phase 2: local stats (Mc, Sc), publish, handshake ----
    float ev = (tid < len) ? es[tid] : -INFINITY;
    red[tid] = ev;
    __syncthreads();
    for (int s2 = 128; s2 > 0; s2 >>= 1) {
        if (tid < s2) red[tid] = fmaxf(red[tid], red[tid + s2]);
        __syncthreads();
    }
    float Mc = red[0];
    __syncthreads();
    red[tid] = (tid < len) ? expf(ev - Mc) : 0.f;
    __syncthreads();
    for (int s2 = 128; s2 > 0; s2 >>= 1) {
        if (tid < s2) red[tid] += red[tid + s2];
        __syncthreads();
    }
    float Sc = red[0];
    if (tid == 0) {
        g_stat[b * 8 + chunk * 2 + 0] = Mc;
        g_stat[b * 8 + chunk * 2 + 1] = Sc;
        __threadfence();
        atomicAdd(&g_cnt[b], 1);
        int target = 4 * (t + 1);
        while (((volatile int*)g_cnt)[b] < target) __nanosleep(64);
    }
    __syncthreads();
    __threadfence();
    float m0 = __ldcg(&g_stat[b * 8 + 0]), s0 = __ldcg(&g_stat[b * 8 + 1]);
    float m1 = __ldcg(&g_stat[b * 8 + 2]), s1 = __ldcg(&g_stat[b * 8 + 3]);
    float m2 = __ldcg(&g_stat[b * 8 + 4]), s2v = __ldcg(&g_stat[b * 8 + 5]);
    float m3 = __ldcg(&g_stat[b * 8 + 6]), s3 = __ldcg(&g_stat[b * 8 + 7]);
    float M = fmaxf(fmaxf(m0, m1), fmaxf(m2, m3));
    float S = ((s0 * expf(m0 - M) + s1 * expf(m1 - M)) + s2v * expf(m2 - M)) + s3 * expf(m3 - M);
    float inv = 1.f / S;
    if (tid < len) es[tid] = expf(ev - M) * inv;
    __syncthreads();
    // ---- phase 3: awe partial for this chunk over all 512 cols ----
    int cq = tid & 127, pg = tid >> 7;
    const float4* eb = (const float4*)(enc + (size_t)b * NP * NENC + (size_t)pstart * NENC) + cq;
    float4 acc = make_float4(0.f, 0.f, 0.f, 0.f);
#pragma unroll 8
    for (int p = pg; p < len; p += 2) {
        float al = es[p];
        float4 v = eb[(size_t)p * 128];
        acc.x += al * v.x;
        acc.y += al * v.y;
        acc.z += al * v.z;
        acc.w += al * v.w;
    }
    if (pg == 1) part[cq] = acc;
    __syncthreads();
    if (pg == 0) {
        float4 pv = part[cq];
        acc.x += pv.x;
        acc.y += pv.y;
        acc.z += pv.z;
        acc.w += pv.w;
        ((float4*)(g_xp[chunk] + b * NENC))[cq] = acc;
    }
}

// ---------------- K3: combine awe partials + gate -> g_x ----------------
__global__ void k_comb(const float* __restrict__ bb) {
    int b = blockIdx.x, c = threadIdx.x;  // 512 threads
    float aw = ((g_xp[0][b * NENC + c] + g_xp[1][b * NENC + c]) + g_xp[2][b * NENC + c]) +
               g_xp[3][b * NENC + c];
    float gt = sigmoidf_(g_gtp[0][b * NENC + c] + g_gtp[1][b * NENC + c] + g_gtp[2][b * NENC + c] +
                         g_gtp[3][b * NENC + c] + bb[c]);
    g_x[b * NENC + c] = aw * gt;
}

// ---------------- K4: awe @ Wih[256:768]  (64 col-tiles x 4 K-splits) ----------------
__global__ __launch_bounds__(256, 2) void k_wih(const float* __restrict__ Wih) {
    __shared__ __align__(16) float As[KC * 128];
    __shared__ __align__(16) float2 Bs[KC * 32];
    int bx = blockIdx.x;
    int ks = bx & 3, tile = bx >> 2;
    unsigned long long acc[8];
    gemm128x32(g_x + ks * 128, NH, Wih + (size_t)(NE + ks * 128) * NG, NG, tile * 32, 128, acc,
               As, Bs);
    store_tile_raw(g_wp[ks], NG, tile * 32, acc);
}

// ---------------- K5: gate-sum + LSTM + preds + argmax + token feedback ----------------
__global__ __launch_bounds__(512) void k_step(const float* __restrict__ bfc,
                                              float* __restrict__ out, int t) {
    int b = blockIdx.x, tid = threadIdx.x, wid = tid >> 5, lane = tid & 31;
    __shared__ __align__(16) float hs[NH];
    __shared__ float pv[128];
    __shared__ int pi_[128];
    int tok = g_tok[b];
    {
        int j = tid;
        const float* ew = g_embW + tok * NG;
#pragma unroll
        for (int gix = 0; gix < 1; gix++) {}
        float gv4[4];
#pragma unroll
        for (int gi = 0; gi < 4; gi++) {
            int jj = j + gi * 512;
            float v = ((g_gw[0][b * NG + jj] + g_gw[1][b * NG + jj]) + g_gw[2][b * NG + jj]) +
                      g_gw[3][b * NG + jj];
            v += ((g_wp[0][b * NG + jj] + g_wp[1][b * NG + jj]) + g_wp[2][b * NG + jj]) +
                 g_wp[3][b * NG + jj];
            v += ew[jj] + g_lstmb[jj];
            gv4[gi] = v;
        }
        float c = g_c[b * NH + j];
        float cn = sigmoidf_(gv4[1]) * c + sigmoidf_(gv4[0]) * tanhf(gv4[2]);
        float hn = sigmoidf_(gv4[3]) * tanhf(cn);
        g_c[b * NH + j] = cn;
        g_h[b * NH + j] = hn;
        hs[j] = hn;
    }
    if (tid < 128) {
        pv[tid] = -INFINITY;
        pi_[tid] = tid;
    }
    __syncthreads();
    int done = g_done[0];
    const float4* hs4 = (const float4*)hs;
    for (int col = wid; col < NV; col += 16) {
        const float4* wr = (const float4*)(g_WfcT + col * NH);
        float s = 0.f;
#pragma unroll
        for (int i = 0; i < 4; i++) {
            float4 h4 = hs4[lane + 32 * i];
            float4 w4 = wr[lane + 32 * i];
            s += h4.x * w4.x + h4.y * w4.y + h4.z * w4.z + h4.w * w4.w;
        }
#pragma unroll
        for (int o = 16; o > 0; o >>= 1) s += __shfl_down_sync(0xffffffffu, s, o);
        if (lane == 0) {
            s += bfc[col];
            out[(size_t)b * NT * NV + (size_t)t * NV + col] = done ? 0.f : s;
            pv[col] = s;
            pi_[col] = col;
        }
    }
    __syncthreads();
    for (int s2 = 64; s2 > 0; s2 >>= 1) {
        if (tid < s2) {
            float ov = pv[tid + s2];
            int oi = pi_[tid + s2];
            if (ov > pv[tid] || (ov == pv[tid] && oi < pi_[tid])) {
                pv[tid] = ov;
                pi_[tid] = oi;
            }
        }
        __syncthreads();
    }
    if (tid == 0) {
        g_rowval[b] = pv[0];
        g_rowflat[b] = b * NV + pi_[0];
        g_tok[b] = pi_[0];
    }
}

extern "C" void kernel_launch(void* const* d_in, const int* in_sizes, int n_in,
                              void* d_out, int out_size) {
    (void)in_sizes; (void)n_in; (void)out_size;
    const float* enc = (const float*)d_in[0];
    const float* emb = (const float*)d_in[1];
    const float* We  = (const float*)d_in[2];
    const float* be  = (const float*)d_in[3];
    const float* Wd  = (const float*)d_in[4];
    const float* bd  = (const float*)d_in[5];
    const float* wf  = (const float*)d_in[6];
    const float* Wh0 = (const float*)d_in[8];
    const float* bh0 = (const float*)d_in[9];
    const float* Wc0 = (const float*)d_in[10];
    const float* bc0 = (const float*)d_in[11];
    const float* Wb  = (const float*)d_in[12];
    const float* bb  = (const float*)d_in[13];
    const float* Wih = (const float*)d_in[14];
    const float* Whh = (const float*)d_in[15];
    const float* bih = (const float*)d_in[16];
    const float* bhh = (const float*)d_in[17];
    const float* Wfc = (const float*)d_in[18];
    const float* bfc = (const float*)d_in[19];
    float* out = (float*)d_out;

    k_init<<<NB + NV + 4 + NV * 4, 512>>>(enc, Wfc, bih, bhh, emb, Wih);
    k_att1<<<5032, 256>>>(enc, We, be, Wh0, bh0, Wc0, bc0);
    for (int t = 0; t < NT; t++) {
        k_gemms<<<352, 256>>>(Wd, Whh, Wb);
        k_att<<<512, 256>>>(enc, wf, bd, t);
        k_comb<<<NB, 512>>>(bb);
        k_wih<<<256, 256>>>(Wih);
        k_step<<<NB, 512>>>(bfc, out, t);
    }
}